// round 15
// baseline (speedup 1.0000x reference)
#include <cuda_runtime.h>
#include <cstdint>

#define NNODES 40000
#define INDIM  128
#define HID    64
#define NEDGES 640000
#define SLOT_SHIFT 7           // 128 slots per node

typedef unsigned long long ull;

// ---------------- scratch (device globals) ----------------
__device__ float g_y[NNODES * HID];       // lin_l(x) per node
__device__ float g_r[NNODES * HID];       // lin_r(x) per node
__device__ float g_h[NNODES * HID];       // layer-1 activation
__device__ int   g_deg[NNODES];           // zero-init; re-zeroed by pull2
__device__ int   g_csr[NNODES << SLOT_SHIFT];
// packed bf16 hi/lo of combined weights [n=128][k], u32 = 2 bf16 (lo = even k)
__device__ uint32_t g_W1h[128 * 64], g_W1l[128 * 64];   // KI=128 -> 64 u32/row
__device__ uint32_t g_W2h[128 * 32], g_W2l[128 * 32];   // KI=64  -> 32 u32/row

// ---------------- bf16 split helpers ----------------
// pack {hi16 = bf16(x1), lo16 = bf16(x0)}  (x0 = even-k element)
__device__ __forceinline__ void split2(float x0, float x1,
                                       uint32_t& h, uint32_t& l) {
    asm("cvt.rn.bf16x2.f32 %0, %1, %2;" : "=r"(h) : "f"(x1), "f"(x0));
    float h0 = __uint_as_float(h << 16);
    float h1 = __uint_as_float(h & 0xffff0000u);
    asm("cvt.rn.bf16x2.f32 %0, %1, %2;" : "=r"(l) : "f"(x1 - h1), "f"(x0 - h0));
}

__device__ __forceinline__ void mma16816(float* c, const uint32_t* a,
                                         const uint32_t* b) {
    asm volatile(
        "mma.sync.aligned.m16n8k16.row.col.f32.bf16.bf16.f32 "
        "{%0,%1,%2,%3}, {%4,%5,%6,%7}, {%8,%9}, {%0,%1,%2,%3};\n"
        : "+f"(c[0]), "+f"(c[1]), "+f"(c[2]), "+f"(c[3])
        : "r"(a[0]), "r"(a[1]), "r"(a[2]), "r"(a[3]), "r"(b[0]), "r"(b[1]));
}

// ---------------- W prep: fp32 -> packed bf16 hi/lo ----------------
__global__ void k_prepW(const float* __restrict__ W1l_, const float* __restrict__ W1r_,
                        const float* __restrict__ W2l_, const float* __restrict__ W2r_) {
    int i = blockIdx.x * blockDim.x + threadIdx.x;
    if (i < 128 * 64) {                       // layer 1: n = i/64, kk = i%64
        int n = i >> 6, kk = i & 63;
        const float* src = (n < HID) ? (W1l_ + n * INDIM) : (W1r_ + (n - HID) * INDIM);
        uint32_t h, l;
        split2(src[2 * kk], src[2 * kk + 1], h, l);
        g_W1h[i] = h; g_W1l[i] = l;
    }
    if (i < 128 * 32) {                       // layer 2: n = i/32, kk = i%32
        int n = i >> 5, kk = i & 31;
        const float* src = (n < HID) ? (W2l_ + n * HID) : (W2r_ + (n - HID) * HID);
        uint32_t h, l;
        split2(src[2 * kk], src[2 * kk + 1], h, l);
        g_W2h[i] = h; g_W2l[i] = l;
    }
}

// ---------------- fused CSR build: count + slot scatter ----------------
__global__ void k_build(const int* __restrict__ ei) {
    int i = blockIdx.x * blockDim.x + threadIdx.x;
    if (i >= NEDGES / 4) return;
    int4 s = ((const int4*)ei)[i];
    int4 d = ((const int4*)(ei + NEDGES))[i];
    int r;
    r = atomicAdd(&g_deg[d.x], 1); g_csr[(d.x << SLOT_SHIFT) + r] = s.x;
    r = atomicAdd(&g_deg[d.y], 1); g_csr[(d.y << SLOT_SHIFT) + r] = s.y;
    r = atomicAdd(&g_deg[d.z], 1); g_csr[(d.z << SLOT_SHIFT) + r] = s.z;
    r = atomicAdd(&g_deg[d.w], 1); g_csr[(d.w << SLOT_SHIFT) + r] = s.w;
}

// ---------------- tensor-core dual GEMM: [Y|R] = X @ [Wl|Wr]^T --------
// Block: 64 rows x 128 cols, 256 threads = 8 warps (2 row x 4 col), each
// warp 32x32 via m16n8k16 bf16 mma, split-bf16 (3 products, lo*lo dropped).
// Smem u32 layout, KP2 = KI/2+4 pad (bank-conflict-free: 4g+tig distinct).
template <int KI, bool FROMH>
__global__ __launch_bounds__(256) void k_gemm_mma(const float* __restrict__ Xin) {
    constexpr int KP2 = KI / 2 + 4;
    extern __shared__ uint32_t smem[];
    uint32_t* sXh = smem;
    uint32_t* sXl = sXh + 64 * KP2;
    uint32_t* sWh = sXl + 64 * KP2;
    uint32_t* sWl = sWh + 128 * KP2;

    const float* __restrict__ X = FROMH ? (const float*)g_h : Xin;
    const uint32_t* __restrict__ gWh = FROMH ? g_W2h : g_W1h;
    const uint32_t* __restrict__ gWl = FROMH ? g_W2l : g_W1l;

    const int t = threadIdx.x;
    const int rowBase = blockIdx.x << 6;

    // ---- stage X (convert fp32 -> bf16 hi/lo) ----
    {
        const int lrow = t >> 2, px = t & 3;
        const float* Xg = X + (size_t)(rowBase + lrow) * KI + px * (KI / 4);
        uint32_t* dXh = sXh + lrow * KP2 + px * (KI / 8);
        uint32_t* dXl = sXl + lrow * KP2 + px * (KI / 8);
#pragma unroll
        for (int j = 0; j < KI / 16; j++) {
            float4 v = ((const float4*)Xg)[j];
            uint32_t h0, l0, h1, l1;
            split2(v.x, v.y, h0, l0);
            split2(v.z, v.w, h1, l1);
            *(uint2*)(dXh + j * 2) = make_uint2(h0, h1);
            *(uint2*)(dXl + j * 2) = make_uint2(l0, l1);
        }
    }
    // ---- stage W (copy prepped bf16) ----
    {
        const int wrow = t >> 1, half = t & 1;
        const uint32_t* srcH = gWh + wrow * (KI / 2) + half * (KI / 4);
        const uint32_t* srcL = gWl + wrow * (KI / 2) + half * (KI / 4);
        uint32_t* dWh = sWh + wrow * KP2 + half * (KI / 4);
        uint32_t* dWl = sWl + wrow * KP2 + half * (KI / 4);
#pragma unroll
        for (int j = 0; j < KI / 8; j++) {
            *(uint2*)(dWh + j * 2) = *(const uint2*)(srcH + j * 2);
            *(uint2*)(dWl + j * 2) = *(const uint2*)(srcL + j * 2);
        }
    }
    __syncthreads();

    const int warp = t >> 5;
    const int warpRow = warp & 1;        // 2 x 32 rows
    const int warpCol = warp >> 1;       // 4 x 32 cols
    const int lane = t & 31;
    const int g = lane >> 2, tig = lane & 3;

    float acc[2][4][4];
#pragma unroll
    for (int a = 0; a < 2; a++)
#pragma unroll
        for (int b = 0; b < 4; b++)
#pragma unroll
            for (int c = 0; c < 4; c++) acc[a][b][c] = 0.f;

#pragma unroll
    for (int kc = 0; kc < KI / 16; kc++) {
        uint32_t Ah[2][4], Al[2][4], Bh[4][2], Bl[4][2];
#pragma unroll
        for (int mt = 0; mt < 2; mt++) {
            int base = (warpRow * 32 + mt * 16 + g) * KP2 + kc * 8 + tig;
            Ah[mt][0] = sXh[base];            Ah[mt][1] = sXh[base + 8 * KP2];
            Ah[mt][2] = sXh[base + 4];        Ah[mt][3] = sXh[base + 8 * KP2 + 4];
            Al[mt][0] = sXl[base];            Al[mt][1] = sXl[base + 8 * KP2];
            Al[mt][2] = sXl[base + 4];        Al[mt][3] = sXl[base + 8 * KP2 + 4];
        }
#pragma unroll
        for (int nt = 0; nt < 4; nt++) {
            int base = (warpCol * 32 + nt * 8 + g) * KP2 + kc * 8 + tig;
            Bh[nt][0] = sWh[base];            Bh[nt][1] = sWh[base + 4];
            Bl[nt][0] = sWl[base];            Bl[nt][1] = sWl[base + 4];
        }
#pragma unroll
        for (int mt = 0; mt < 2; mt++)
#pragma unroll
            for (int nt = 0; nt < 4; nt++) {
                mma16816(acc[mt][nt], Ah[mt], Bh[nt]);
                mma16816(acc[mt][nt], Ah[mt], Bl[nt]);
                mma16816(acc[mt][nt], Al[mt], Bh[nt]);
            }
    }

    // ---- epilogue: cols<64 -> g_y, else g_r ----
#pragma unroll
    for (int nt = 0; nt < 4; nt++) {
        int c = warpCol * 32 + nt * 8 + 2 * tig;
        float* O = (c < HID) ? (g_y + c) : (g_r + (c - HID));
#pragma unroll
        for (int mt = 0; mt < 2; mt++) {
            int row = rowBase + warpRow * 32 + mt * 16 + g;
            *(float2*)(O + (size_t)row * HID) =
                make_float2(acc[mt][nt][0], acc[mt][nt][1]);
            *(float2*)(O + (size_t)(row + 8) * HID) =
                make_float2(acc[mt][nt][2], acc[mt][nt][3]);
        }
    }
}

// ---------------- pull aggregation fused with epilogue ----------------
template <bool RELU, bool TOH, bool ZERODEG>
__global__ __launch_bounds__(256) void k_pull(
    const float* __restrict__ bias, float* __restrict__ outp) {
    int w = (blockIdx.x * blockDim.x + threadIdx.x) >> 5;
    int lane = threadIdx.x & 31;
    if (w >= NNODES) return;

    const int deg = g_deg[w];
    const int beg = w << SLOT_SHIFT;
    float2 acc = make_float2(0.f, 0.f);

    for (int base = 0; base < deg; base += 32) {
        int idx = base + lane;
        int my = (idx < deg) ? g_csr[beg + idx] : 0;
        int m = min(32, deg - base);
#pragma unroll 4
        for (int j = 0; j < m; j++) {
            int s = __shfl_sync(0xffffffffu, my, j);
            float2 v = *(const float2*)(g_y + (size_t)s * HID + lane * 2);
            acc.x += v.x; acc.y += v.y;
        }
    }

    if (ZERODEG && lane == 0) g_deg[w] = 0;

    float inv = 1.0f / fmaxf((float)deg, 1.0f);
    float2 r = *(const float2*)(g_r + (size_t)w * HID + lane * 2);
    float2 b = *(const float2*)(bias + lane * 2);
    float2 o;
    o.x = fmaf(acc.x, inv, r.x + b.x);
    o.y = fmaf(acc.y, inv, r.y + b.y);
    if (RELU) { o.x = fmaxf(o.x, 0.f); o.y = fmaxf(o.y, 0.f); }
    float* dstp = TOH ? (g_h + (size_t)w * HID + lane * 2)
                      : (outp + (size_t)w * HID + lane * 2);
    *(float2*)dstp = o;
}

// ---------------- launch ----------------
extern "C" void kernel_launch(void* const* d_in, const int* in_sizes, int n_in,
                              void* d_out, int out_size) {
    const float* x   = (const float*)d_in[0];
    const int*   ei  = (const int*)d_in[1];
    const float* W1l = (const float*)d_in[2];
    const float* b1  = (const float*)d_in[3];
    const float* W1r = (const float*)d_in[4];
    const float* W2l = (const float*)d_in[5];
    const float* b2  = (const float*)d_in[6];
    const float* W2r = (const float*)d_in[7];
    float* out = (float*)d_out;

    constexpr int KP1 = INDIM / 2 + 4, KP2c = HID / 2 + 4;
    constexpr int SMEM1 = (64 * KP1 * 2 + 128 * KP1 * 2) * 4;   // 104448
    constexpr int SMEM2 = (64 * KP2c * 2 + 128 * KP2c * 2) * 4; // 55296

    const int gGemm = NNODES / 64;                 // 625
    const int gPull = (NNODES * 32 + 255) / 256;   // 5000
    const int gE4   = (NEDGES / 4 + 255) / 256;    // 625

    static cudaStream_t s2 = nullptr;
    static cudaEvent_t  eFork = nullptr, eJoin = nullptr;
    static bool forked = false;
    if (!s2) {
        cudaFuncSetAttribute(k_gemm_mma<INDIM, false>,
                             cudaFuncAttributeMaxDynamicSharedMemorySize, SMEM1);
        cudaFuncSetAttribute(k_gemm_mma<HID, true>,
                             cudaFuncAttributeMaxDynamicSharedMemorySize, SMEM2);
        if (cudaStreamCreateWithFlags(&s2, cudaStreamNonBlocking) == cudaSuccess &&
            cudaEventCreateWithFlags(&eFork, cudaEventDisableTiming) == cudaSuccess &&
            cudaEventCreateWithFlags(&eJoin, cudaEventDisableTiming) == cudaSuccess)
            forked = true;
    }

    if (forked) {
        cudaEventRecord(eFork, 0);
        cudaStreamWaitEvent(s2, eFork, 0);
        k_build<<<gE4, 256, 0, s2>>>(ei);
        cudaEventRecord(eJoin, s2);

        k_prepW<<<32, 256>>>(W1l, W1r, W2l, W2r);
        k_gemm_mma<INDIM, false><<<gGemm, 256, SMEM1>>>(x);

        cudaStreamWaitEvent(0, eJoin, 0);
    } else {
        k_build<<<gE4, 256>>>(ei);
        k_prepW<<<32, 256>>>(W1l, W1r, W2l, W2r);
        k_gemm_mma<INDIM, false><<<gGemm, 256, SMEM1>>>(x);
    }

    // layer 1 aggregate + epilogue
    k_pull<true, true, false><<<gPull, 256>>>(b1, nullptr);

    // layer 2
    k_gemm_mma<HID, true><<<gGemm, 256, SMEM2>>>(nullptr);
    k_pull<false, false, true><<<gPull, 256>>>(b2, out);
}

// round 16
// speedup vs baseline: 1.0476x; 1.0476x over previous
#include <cuda_runtime.h>
#include <cstdint>

#define NNODES 40000
#define INDIM  128
#define HID    64
#define NEDGES 640000
#define SLOT_SHIFT 7           // 128 slots per node

typedef unsigned long long ull;

// ---------------- scratch (device globals) ----------------
__device__ float g_y[NNODES * HID];       // lin_l(x) per node
__device__ float g_r[NNODES * HID];       // lin_r(x) per node
__device__ float g_h[NNODES * HID];       // layer-1 activation
__device__ int   g_deg[NNODES];           // zero-init; re-zeroed by pull2
__device__ int   g_csr[NNODES << SLOT_SHIFT];
// packed bf16 hi/lo of combined weights [n=128][k], u32 = 2 bf16 (lo = even k)
__device__ uint32_t g_W1h[128 * 64], g_W1l[128 * 64];   // KI=128 -> 64 u32/row
__device__ uint32_t g_W2h[128 * 32], g_W2l[128 * 32];   // KI=64  -> 32 u32/row

// ---------------- bf16 split helpers ----------------
__device__ __forceinline__ void split2(float x0, float x1,
                                       uint32_t& h, uint32_t& l) {
    asm("cvt.rn.bf16x2.f32 %0, %1, %2;" : "=r"(h) : "f"(x1), "f"(x0));
    float h0 = __uint_as_float(h << 16);
    float h1 = __uint_as_float(h & 0xffff0000u);
    asm("cvt.rn.bf16x2.f32 %0, %1, %2;" : "=r"(l) : "f"(x1 - h1), "f"(x0 - h0));
}

__device__ __forceinline__ void mma16816(float* c, const uint32_t* a,
                                         const uint32_t* b) {
    asm volatile(
        "mma.sync.aligned.m16n8k16.row.col.f32.bf16.bf16.f32 "
        "{%0,%1,%2,%3}, {%4,%5,%6,%7}, {%8,%9}, {%0,%1,%2,%3};\n"
        : "+f"(c[0]), "+f"(c[1]), "+f"(c[2]), "+f"(c[3])
        : "r"(a[0]), "r"(a[1]), "r"(a[2]), "r"(a[3]), "r"(b[0]), "r"(b[1]));
}

// ---------------- W prep: fp32 -> packed bf16 hi/lo ----------------
__global__ void k_prepW(const float* __restrict__ W1l_, const float* __restrict__ W1r_,
                        const float* __restrict__ W2l_, const float* __restrict__ W2r_) {
    int i = blockIdx.x * blockDim.x + threadIdx.x;
    if (i < 128 * 64) {
        int n = i >> 6, kk = i & 63;
        const float* src = (n < HID) ? (W1l_ + n * INDIM) : (W1r_ + (n - HID) * INDIM);
        uint32_t h, l;
        split2(src[2 * kk], src[2 * kk + 1], h, l);
        g_W1h[i] = h; g_W1l[i] = l;
    }
    if (i < 128 * 32) {
        int n = i >> 5, kk = i & 31;
        const float* src = (n < HID) ? (W2l_ + n * HID) : (W2r_ + (n - HID) * HID);
        uint32_t h, l;
        split2(src[2 * kk], src[2 * kk + 1], h, l);
        g_W2h[i] = h; g_W2l[i] = l;
    }
}

// ---------------- fused CSR build: count + slot scatter ----------------
__global__ void k_build(const int* __restrict__ ei) {
    int i = blockIdx.x * blockDim.x + threadIdx.x;
    if (i >= NEDGES / 4) return;
    int4 s = ((const int4*)ei)[i];
    int4 d = ((const int4*)(ei + NEDGES))[i];
    int r;
    r = atomicAdd(&g_deg[d.x], 1); g_csr[(d.x << SLOT_SHIFT) + r] = s.x;
    r = atomicAdd(&g_deg[d.y], 1); g_csr[(d.y << SLOT_SHIFT) + r] = s.y;
    r = atomicAdd(&g_deg[d.z], 1); g_csr[(d.z << SLOT_SHIFT) + r] = s.z;
    r = atomicAdd(&g_deg[d.w], 1); g_csr[(d.w << SLOT_SHIFT) + r] = s.w;
}

// ---------------- tensor-core dual GEMM: [Y|R] = X @ [Wl|Wr]^T --------
// Block 64 rows x 128 cols, 8 warps (2x4), warp 32x32 m16n8k16 split-bf16.
// X staged in smem (hi/lo); B fragments read directly from prepped W via
// __ldg (64KB, L1-resident, shared by all blocks) -> smem 35KB/18KB.
template <int KI, bool FROMH>
__global__ __launch_bounds__(256) void k_gemm_mma(const float* __restrict__ Xin) {
    constexpr int KP2 = KI / 2 + 4;
    extern __shared__ uint32_t smem[];
    uint32_t* sXh = smem;
    uint32_t* sXl = sXh + 64 * KP2;

    const float* __restrict__ X = FROMH ? (const float*)g_h : Xin;
    const uint32_t* __restrict__ gWh = FROMH ? g_W2h : g_W1h;
    const uint32_t* __restrict__ gWl = FROMH ? g_W2l : g_W1l;

    const int t = threadIdx.x;
    const int rowBase = blockIdx.x << 6;

    // ---- stage X (convert fp32 -> bf16 hi/lo) ----
    {
        const int lrow = t >> 2, px = t & 3;
        const float* Xg = X + (size_t)(rowBase + lrow) * KI + px * (KI / 4);
        uint32_t* dXh = sXh + lrow * KP2 + px * (KI / 8);
        uint32_t* dXl = sXl + lrow * KP2 + px * (KI / 8);
#pragma unroll
        for (int j = 0; j < KI / 16; j++) {
            float4 v = ((const float4*)Xg)[j];
            uint32_t h0, l0, h1, l1;
            split2(v.x, v.y, h0, l0);
            split2(v.z, v.w, h1, l1);
            *(uint2*)(dXh + j * 2) = make_uint2(h0, h1);
            *(uint2*)(dXl + j * 2) = make_uint2(l0, l1);
        }
    }
    __syncthreads();

    const int warp = t >> 5;
    const int warpRow = warp & 1;        // 2 x 32 rows
    const int warpCol = warp >> 1;       // 4 x 32 cols
    const int lane = t & 31;
    const int g = lane >> 2, tig = lane & 3;

    float acc[2][4][4];
#pragma unroll
    for (int a = 0; a < 2; a++)
#pragma unroll
        for (int b = 0; b < 4; b++)
#pragma unroll
            for (int c = 0; c < 4; c++) acc[a][b][c] = 0.f;

#pragma unroll
    for (int kc = 0; kc < KI / 16; kc++) {
        uint32_t Ah[2][4], Al[2][4], Bh[4][2], Bl[4][2];
#pragma unroll
        for (int mt = 0; mt < 2; mt++) {
            int base = (warpRow * 32 + mt * 16 + g) * KP2 + kc * 8 + tig;
            Ah[mt][0] = sXh[base];            Ah[mt][1] = sXh[base + 8 * KP2];
            Ah[mt][2] = sXh[base + 4];        Ah[mt][3] = sXh[base + 8 * KP2 + 4];
            Al[mt][0] = sXl[base];            Al[mt][1] = sXl[base + 8 * KP2];
            Al[mt][2] = sXl[base + 4];        Al[mt][3] = sXl[base + 8 * KP2 + 4];
        }
#pragma unroll
        for (int nt = 0; nt < 4; nt++) {
            int base = (warpCol * 32 + nt * 8 + g) * (KI / 2) + kc * 8 + tig;
            Bh[nt][0] = __ldg(&gWh[base]);    Bh[nt][1] = __ldg(&gWh[base + 4]);
            Bl[nt][0] = __ldg(&gWl[base]);    Bl[nt][1] = __ldg(&gWl[base + 4]);
        }
#pragma unroll
        for (int mt = 0; mt < 2; mt++)
#pragma unroll
            for (int nt = 0; nt < 4; nt++) {
                mma16816(acc[mt][nt], Ah[mt], Bh[nt]);
                mma16816(acc[mt][nt], Ah[mt], Bl[nt]);
                mma16816(acc[mt][nt], Al[mt], Bh[nt]);
            }
    }

    // ---- epilogue: cols<64 -> g_y, else g_r ----
#pragma unroll
    for (int nt = 0; nt < 4; nt++) {
        int c = warpCol * 32 + nt * 8 + 2 * tig;
        float* O = (c < HID) ? (g_y + c) : (g_r + (c - HID));
#pragma unroll
        for (int mt = 0; mt < 2; mt++) {
            int row = rowBase + warpRow * 32 + mt * 16 + g;
            *(float2*)(O + (size_t)row * HID) =
                make_float2(acc[mt][nt][0], acc[mt][nt][1]);
            *(float2*)(O + (size_t)(row + 8) * HID) =
                make_float2(acc[mt][nt][2], acc[mt][nt][3]);
        }
    }
}

// ---------------- pull aggregation fused with epilogue ----------------
// One warp per node. Slot indices fetched coalesced (32 at a time) and
// shfl-broadcast; inner loop processes 2 neighbors/iteration: lanes 0-15
// gather neighbor j (float4 = 16x16B), lanes 16-31 neighbor j+1.
// Halves combined with one shfl_xor(16); half 0 does the epilogue.
template <bool RELU, bool TOH, bool ZERODEG>
__global__ __launch_bounds__(256) void k_pull(
    const float* __restrict__ bias, float* __restrict__ outp) {
    int w = (blockIdx.x * blockDim.x + threadIdx.x) >> 5;
    int lane = threadIdx.x & 31;
    if (w >= NNODES) return;

    const int deg  = g_deg[w];
    const int beg  = w << SLOT_SHIFT;
    const int half = lane >> 4;
    const int hl   = lane & 15;

    float4 acc = make_float4(0.f, 0.f, 0.f, 0.f);

    for (int base = 0; base < deg; base += 32) {
        int idx = base + lane;
        int my = (idx < deg) ? g_csr[beg + idx] : 0;   // coalesced slot row
        int m = min(32, deg - base);
#pragma unroll 4
        for (int j = 0; j < m; j += 2) {
            int s = __shfl_sync(0xffffffffu, my, j + half);
            if (half == 0 || j + 1 < m) {
                float4 v = *(const float4*)(g_y + (size_t)s * HID + hl * 4);
                acc.x += v.x; acc.y += v.y; acc.z += v.z; acc.w += v.w;
            }
        }
    }

    acc.x += __shfl_xor_sync(0xffffffffu, acc.x, 16);
    acc.y += __shfl_xor_sync(0xffffffffu, acc.y, 16);
    acc.z += __shfl_xor_sync(0xffffffffu, acc.z, 16);
    acc.w += __shfl_xor_sync(0xffffffffu, acc.w, 16);

    if (ZERODEG && lane == 0) g_deg[w] = 0;   // restore invariant (after reads)

    if (half == 0) {
        float inv = 1.0f / fmaxf((float)deg, 1.0f);
        float4 r = *(const float4*)(g_r + (size_t)w * HID + hl * 4);
        float4 b = *(const float4*)(bias + hl * 4);
        float4 o;
        o.x = fmaf(acc.x, inv, r.x + b.x);
        o.y = fmaf(acc.y, inv, r.y + b.y);
        o.z = fmaf(acc.z, inv, r.z + b.z);
        o.w = fmaf(acc.w, inv, r.w + b.w);
        if (RELU) {
            o.x = fmaxf(o.x, 0.f); o.y = fmaxf(o.y, 0.f);
            o.z = fmaxf(o.z, 0.f); o.w = fmaxf(o.w, 0.f);
        }
        float* dstp = TOH ? (g_h + (size_t)w * HID + hl * 4)
                          : (outp + (size_t)w * HID + hl * 4);
        *(float4*)dstp = o;
    }
}

// ---------------- launch ----------------
extern "C" void kernel_launch(void* const* d_in, const int* in_sizes, int n_in,
                              void* d_out, int out_size) {
    const float* x   = (const float*)d_in[0];
    const int*   ei  = (const int*)d_in[1];
    const float* W1l = (const float*)d_in[2];
    const float* b1  = (const float*)d_in[3];
    const float* W1r = (const float*)d_in[4];
    const float* W2l = (const float*)d_in[5];
    const float* b2  = (const float*)d_in[6];
    const float* W2r = (const float*)d_in[7];
    float* out = (float*)d_out;

    constexpr int KP1 = INDIM / 2 + 4, KP2c = HID / 2 + 4;
    constexpr int SMEM1 = 64 * KP1 * 2 * 4;    // 34816
    constexpr int SMEM2 = 64 * KP2c * 2 * 4;   // 18432

    const int gGemm = NNODES / 64;                 // 625
    const int gPull = (NNODES * 32 + 255) / 256;   // 5000
    const int gE4   = (NEDGES / 4 + 255) / 256;    // 625

    static cudaStream_t s2 = nullptr;
    static cudaEvent_t  eFork = nullptr, eJoin = nullptr;
    static bool forked = false;
    if (!s2) {
        cudaFuncSetAttribute(k_gemm_mma<INDIM, false>,
                             cudaFuncAttributeMaxDynamicSharedMemorySize, SMEM1);
        cudaFuncSetAttribute(k_gemm_mma<HID, true>,
                             cudaFuncAttributeMaxDynamicSharedMemorySize, SMEM2);
        if (cudaStreamCreateWithFlags(&s2, cudaStreamNonBlocking) == cudaSuccess &&
            cudaEventCreateWithFlags(&eFork, cudaEventDisableTiming) == cudaSuccess &&
            cudaEventCreateWithFlags(&eJoin, cudaEventDisableTiming) == cudaSuccess)
            forked = true;
    }

    if (forked) {
        cudaEventRecord(eFork, 0);
        cudaStreamWaitEvent(s2, eFork, 0);
        k_build<<<gE4, 256, 0, s2>>>(ei);
        cudaEventRecord(eJoin, s2);

        k_prepW<<<32, 256>>>(W1l, W1r, W2l, W2r);
        k_gemm_mma<INDIM, false><<<gGemm, 256, SMEM1>>>(x);

        cudaStreamWaitEvent(0, eJoin, 0);
    } else {
        k_build<<<gE4, 256>>>(ei);
        k_prepW<<<32, 256>>>(W1l, W1r, W2l, W2r);
        k_gemm_mma<INDIM, false><<<gGemm, 256, SMEM1>>>(x);
    }

    // layer 1 aggregate + epilogue
    k_pull<true, true, false><<<gPull, 256>>>(b1, nullptr);

    // layer 2
    k_gemm_mma<HID, true><<<gGemm, 256, SMEM2>>>(nullptr);
    k_pull<false, false, true><<<gPull, 256>>>(b2, out);
}